// round 4
// baseline (speedup 1.0000x reference)
#include <cuda_runtime.h>
#include <cstdint>

// Correlation D=4, S1=S2=1 ; x1,x2:(4,128,256,256) f32 ; out:(4,81,256,256) f32
//
// Block = (4,8,9) = 288 threads, tile 8x32, all 81 displacements.
// Thread (wg,ty,ky): 8 pixels, one ky, 9 kx -> 36 f32x2 accumulators (FFMA2).
// 3-buffer cp.async ring (proven R2 pipeline), one __syncthreads/stage.
// Sliding register window in the inner product keeps regs <= 113 so that
// 2 CTAs/SM are resident (2 x 100.5KB smem = 201KB < 228KB).

#define Himg 256
#define Wimg 256
#define Cimg 128
#define TH 8
#define TW 32
#define PPT 8
#define CB 8
#define NSTAGE 16
#define S1F 34
#define S2F 50
#define X1_STAGE (CB*TH*S1F)          // 2176 floats
#define X2_STAGE (CB*16*S2F)          // 6400 floats
#define X1_STAGE_B (X1_STAGE*4)
#define X2_STAGE_B (X2_STAGE*4)
#define SMEM_BYTES (3*(X1_STAGE_B + X2_STAGE_B))   // 102912 B
#define CSTRIDE (CB*Himg*Wimg)

typedef unsigned long long ull;

__device__ __forceinline__ void cp_async8(uint32_t dst, const float* src, int sz) {
    asm volatile("cp.async.ca.shared.global [%0], [%1], 8, %2;\n"
                 :: "r"(dst), "l"(src), "r"(sz) : "memory");
}
__device__ __forceinline__ void cp_commit() {
    asm volatile("cp.async.commit_group;\n" ::: "memory");
}
__device__ __forceinline__ ull ffma2(ull a, ull b, ull c) {
    ull d;
    asm("fma.rn.f32x2 %0, %1, %2, %3;" : "=l"(d) : "l"(a), "l"(b), "l"(c));
    return d;
}
__device__ __forceinline__ ull oddpair(ull e0, ull e1) {
    ull r;
    asm("mov.b64 %0, {%1, %2};" : "=l"(r)
        : "r"((unsigned)(e0 >> 32)), "r"((unsigned)e1));
    return r;
}
__device__ __forceinline__ float f2lo(ull a) { return __uint_as_float((unsigned)a); }
__device__ __forceinline__ float f2hi(ull a) { return __uint_as_float((unsigned)(a >> 32)); }

__device__ __forceinline__ void load_stage(bool is_loader,
                                           const float* s2, const float* s1,
                                           uint32_t d2, uint32_t d1,
                                           int szm, int szlo, int szhi) {
    if (is_loader) {
        cp_async8(d2 + 0,  s2 + 0,  szlo);
        cp_async8(d2 + 8,  s2 + 2,  szlo);
        cp_async8(d2 + 16, s2 + 4,  szm);
        cp_async8(d2 + 24, s2 + 6,  szm);
        cp_async8(d2 + 32, s2 + 8,  szm);
        cp_async8(d2 + 40, s2 + 10, szm);
        cp_async8(d2 + 48, s2 + 12, szm);
        cp_async8(d2 + 56, s2 + 14, szm);
        cp_async8(d2 + 64, s2 + 16, szhi);
        cp_async8(d2 + 72, s2 + 18, szhi);
        cp_async8(d1 + 0,  s1 + 0, 8);
        cp_async8(d1 + 8,  s1 + 2, 8);
        cp_async8(d1 + 16, s1 + 4, 8);
        cp_async8(d1 + 24, s1 + 6, 8);
    }
    cp_commit();
}

// One pp row: 9 FFMA2 against the current window (E[pp..pp+4], O[pp..pp+3])
#define ROW9(pp, e0, o0, e1, o1, e2, o2, e3, o3, e4)            \
    do {                                                        \
        acc[pp][0] = ffma2(A, e0, acc[pp][0]);                  \
        acc[pp][1] = ffma2(A, o0, acc[pp][1]);                  \
        acc[pp][2] = ffma2(A, e1, acc[pp][2]);                  \
        acc[pp][3] = ffma2(A, o1, acc[pp][3]);                  \
        acc[pp][4] = ffma2(A, e2, acc[pp][4]);                  \
        acc[pp][5] = ffma2(A, o2, acc[pp][5]);                  \
        acc[pp][6] = ffma2(A, e3, acc[pp][6]);                  \
        acc[pp][7] = ffma2(A, o3, acc[pp][7]);                  \
        acc[pp][8] = ffma2(A, e4, acc[pp][8]);                  \
    } while (0)

__device__ __forceinline__ void compute_stage(const float* x1b, const float* x2b,
                                              ull acc[4][9]) {
    #pragma unroll
    for (int c = 0; c < CB; ++c) {
        const ull* ap = reinterpret_cast<const ull*>(x1b + c * (TH * S1F));
        const ull* vp = reinterpret_cast<const ull*>(x2b + c * (16 * S2F));
        ull E0 = vp[0], E1 = vp[1], E2 = vp[2], E3 = vp[3], E4 = vp[4];
        ull O0 = oddpair(E0, E1), O1 = oddpair(E1, E2);
        ull O2 = oddpair(E2, E3), O3 = oddpair(E3, E4);
        ull A = ap[0];
        ROW9(0, E0, O0, E1, O1, E2, O2, E3, O3, E4);
        ull E5 = vp[5]; ull O4 = oddpair(E4, E5); A = ap[1];
        ROW9(1, E1, O1, E2, O2, E3, O3, E4, O4, E5);
        ull E6 = vp[6]; ull O5 = oddpair(E5, E6); A = ap[2];
        ROW9(2, E2, O2, E3, O3, E4, O4, E5, O5, E6);
        ull E7 = vp[7]; ull O6 = oddpair(E6, E7); A = ap[3];
        ROW9(3, E3, O3, E4, O4, E5, O5, E6, O6, E7);
    }
}

__global__ void __launch_bounds__(288, 2)
corr_kernel(const float* __restrict__ x1, const float* __restrict__ x2,
            float* __restrict__ out) {
    const int wg = threadIdx.x;                 // 0..3
    const int ty = threadIdx.y;                 // 0..7
    const int ky = threadIdx.z;                 // 0..8  (one per warp)
    const int tid = wg + (ty << 2) + (ky << 5);

    const int w0 = blockIdx.x * TW;
    const int h0 = blockIdx.y * TH;
    const int n  = blockIdx.z;

    extern __shared__ float sm[];
    const uint32_t smem_u = (uint32_t)__cvta_generic_to_shared(sm);

    const float* x1n = x1 + (size_t)n * Cimg * Himg * Wimg;
    const float* x2n = x2 + (size_t)n * Cimg * Himg * Wimg;

    // ---------- loader setup (hoisted) ----------
    const bool is_loader = (tid < 256);
    const int li   = tid & 255;
    const int c2   = li >> 5;
    const int rr   = (li >> 1) & 15;
    const int half = li & 1;
    const int hr   = h0 - 4 + rr;
    const int row_ok = ((unsigned)hr < (unsigned)Himg) ? 1 : 0;
    const int hrc  = row_ok ? hr : 0;
    const float* s2 = x2n + ((size_t)(c2 * Himg + hrc)) * Wimg + (w0 - 4) + half * 20;
    const int szm  = row_ok * 8;
    const int szlo = (half == 0 && w0 == 0) ? 0 : szm;
    const int szhi = (half == 1 && w0 == (Wimg - TW)) ? 0 : szm;
    const int r1 = (li >> 2) & 7;
    const int q  = li & 3;
    const float* s1 = x1n + ((size_t)(c2 * Himg + h0 + r1)) * Wimg + w0 + q * 8;
    const uint32_t d2b = smem_u + 3 * X1_STAGE_B + ((c2 * 16 + rr) * S2F + half * 20) * 4;
    const uint32_t d1b = smem_u + ((c2 * TH + r1) * S1F + q * 8) * 4;

    // ---------- compute-side bases ----------
    const float* x1rb = sm + ty * S1F + wg * PPT;
    const float* x2rb = sm + 3 * X1_STAGE + (ty + ky) * S2F + wg * PPT;

    ull acc[4][9];
    #pragma unroll
    for (int pp = 0; pp < 4; ++pp)
        #pragma unroll
        for (int kx = 0; kx < 9; ++kx) acc[pp][kx] = 0ull;

    // ---------- 3-buffer ring pipeline (2-stage prologue) ----------
    load_stage(is_loader, s2, s1, d2b, d1b, szm, szlo, szhi);
    s2 += CSTRIDE; s1 += CSTRIDE;
    load_stage(is_loader, s2, s1, d2b + X2_STAGE_B, d1b + X1_STAGE_B, szm, szlo, szhi);
    s2 += CSTRIDE; s1 += CSTRIDE;

    int bufl = 2;   // load target buffer for stage s+2
    int bufc = 0;   // compute buffer for stage s

    #pragma unroll 1
    for (int s = 0; s < NSTAGE; ++s) {
        if (s < NSTAGE - 1) asm volatile("cp.async.wait_group 1;\n" ::: "memory");
        else                asm volatile("cp.async.wait_group 0;\n" ::: "memory");
        __syncthreads();
        if (s < NSTAGE - 2) {
            load_stage(is_loader, s2, s1,
                       d2b + bufl * X2_STAGE_B, d1b + bufl * X1_STAGE_B,
                       szm, szlo, szhi);
            s2 += CSTRIDE; s1 += CSTRIDE;
            bufl = (bufl == 2) ? 0 : bufl + 1;
        }
        compute_stage(x1rb + bufc * X1_STAGE, x2rb + bufc * X2_STAGE, acc);
        bufc = (bufc == 2) ? 0 : bufc + 1;
    }

    // ---------- epilogue ----------
    const float inv = 1.0f / (float)Cimg;
    float* op = out + ((size_t)(n * 81 + ky * 9) * (Himg * Wimg))
                    + (size_t)(h0 + ty) * Wimg + w0 + wg * PPT;
    #pragma unroll
    for (int kx = 0; kx < 9; ++kx) {
        float4 r0, r1v;
        r0.x  = f2lo(acc[0][kx]) * inv;  r0.y  = f2hi(acc[0][kx]) * inv;
        r0.z  = f2lo(acc[1][kx]) * inv;  r0.w  = f2hi(acc[1][kx]) * inv;
        r1v.x = f2lo(acc[2][kx]) * inv;  r1v.y = f2hi(acc[2][kx]) * inv;
        r1v.z = f2lo(acc[3][kx]) * inv;  r1v.w = f2hi(acc[3][kx]) * inv;
        *reinterpret_cast<float4*>(op + (size_t)kx * (Himg * Wimg))     = r0;
        *reinterpret_cast<float4*>(op + (size_t)kx * (Himg * Wimg) + 4) = r1v;
    }
}

extern "C" void kernel_launch(void* const* d_in, const int* in_sizes, int n_in,
                              void* d_out, int out_size) {
    const float* x1 = (const float*)d_in[0];
    const float* x2 = (const float*)d_in[1];
    float* out = (float*)d_out;

    cudaFuncSetAttribute(corr_kernel, cudaFuncAttributeMaxDynamicSharedMemorySize,
                         SMEM_BYTES);

    dim3 block(4, 8, 9);
    dim3 grid(Wimg / TW, Himg / TH, 4);   // 1024 blocks, target 2 CTAs/SM
    corr_kernel<<<grid, block, SMEM_BYTES>>>(x1, x2, out);
}

// round 5
// speedup vs baseline: 1.6589x; 1.6589x over previous
#include <cuda_runtime.h>
#include <cstdint>

// Correlation D=4, S1=S2=1 ; x1,x2:(4,128,256,256) f32 ; out:(4,81,256,256) f32
//
// R1-proven compute: block (8,8,9)=576 threads, tile 8x32, PPT=4 scalar FFMA,
// 36 fp32 accumulators/thread. New: fully hoisted cp.async loader (3 fixed
// float4 slots/thread + 1 conditional), 3-buffer ring, ONE syncthreads/stage.

#define Himg 256
#define Wimg 256
#define Cimg 128
#define TH 8
#define TW 32
#define CB 8
#define NSTAGE 16
#define S2F 48
#define X1F (CB*TH*TW)        // 2048 floats per buffer (x1 part)
#define X2F (CB*16*S2F)       // 6144 floats per buffer (x2 part)
#define BUFF (X1F + X2F)      // 8192 floats
#define BUFB (BUFF*4)         // 32768 bytes
#define SMEM_BYTES (3*BUFB)   // 98304 bytes
#define CSTRIDE (CB*Himg*Wimg)
#define NTHREADS 576
#define NTASKS 1792           // (64 x1 + 160 x2) float4 per channel * 8

__device__ __forceinline__ void cp_async16(uint32_t dst, const float* src, int sz) {
    asm volatile("cp.async.cg.shared.global [%0], [%1], 16, %2;\n"
                 :: "r"(dst), "l"(src), "r"(sz) : "memory");
}
__device__ __forceinline__ void cp_commit() {
    asm volatile("cp.async.commit_group;\n" ::: "memory");
}

__global__ void __launch_bounds__(NTHREADS, 1)
corr_kernel(const float* __restrict__ x1, const float* __restrict__ x2,
            float* __restrict__ out) {
    const int wg = threadIdx.x;   // 0..7 : 4-pixel group
    const int ty = threadIdx.y;   // 0..7 : row in tile
    const int ky = threadIdx.z;   // 0..8 : displacement row
    const int tid = wg + (ty << 3) + (ky << 6);

    const int w0 = blockIdx.x * TW;
    const int h0 = blockIdx.y * TH;
    const int n  = blockIdx.z;

    extern __shared__ float sm[];
    const uint32_t smem_u = (uint32_t)__cvta_generic_to_shared(sm);

    const float* x1n = x1 + (size_t)n * Cimg * Himg * Wimg;
    const float* x2n = x2 + (size_t)n * Cimg * Himg * Wimg;

    // ---------- loader setup: per-thread fixed slots, computed ONCE ----------
    // task t (< 1792): c = t/224 ; r = t%224
    //   r <  64 : x1 tile   row r/8,  chunk r%8
    //   r >= 64 : x2 halo   row (r-64)/10, chunk (r-64)%10 (zfill at borders)
    const float* lsrc[4];
    uint32_t     ldst[4];
    int          lsz[4];
    #pragma unroll
    for (int k = 0; k < 4; ++k) {
        const int t = tid + k * NTHREADS;
        if (t < NTASKS) {
            const int c = t / 224;
            const int r = t % 224;
            if (r < 64) {
                const int row = r >> 3, v = r & 7;
                lsrc[k] = x1n + ((size_t)(c * Himg + h0 + row)) * Wimg + w0 + v * 4;
                ldst[k] = smem_u + ((c * TH + row) * TW + v * 4) * 4;
                lsz[k]  = 16;
            } else {
                const int r2 = r - 64;
                const int row = r2 / 10, v = r2 % 10;
                const int hr = h0 - 4 + row;
                const int gw = w0 - 4 + v * 4;
                const bool ok = ((unsigned)hr < (unsigned)Himg) && (gw >= 0) && (gw <= Wimg - 4);
                lsrc[k] = x2n + ((size_t)(c * Himg + (ok ? hr : 0))) * Wimg + (ok ? gw : 0);
                ldst[k] = smem_u + (X1F + (c * 16 + row) * S2F + v * 4) * 4;
                lsz[k]  = ok ? 16 : 0;
            }
        } else {
            lsrc[k] = x1n; ldst[k] = smem_u; lsz[k] = -1;  // inactive slot
        }
    }
    const bool has4 = (lsz[3] >= 0);

    // per-stage load: 3 unconditional slots + conditional 4th, then advance
    auto load_stage = [&](int buf) {
        const uint32_t base = buf * BUFB;
        cp_async16(ldst[0] + base, lsrc[0], lsz[0]);
        cp_async16(ldst[1] + base, lsrc[1], lsz[1]);
        cp_async16(ldst[2] + base, lsrc[2], lsz[2]);
        if (has4) cp_async16(ldst[3] + base, lsrc[3], lsz[3]);
        cp_commit();
        lsrc[0] += CSTRIDE; lsrc[1] += CSTRIDE; lsrc[2] += CSTRIDE; lsrc[3] += CSTRIDE;
    };

    // ---------- compute-side bases (R1 layout) ----------
    const float* x1rb = sm + ty * TW + wg * 4;
    const float* x2rb = sm + X1F + (ty + ky) * S2F + wg * 4;

    float acc[4 * 9];
    #pragma unroll
    for (int i = 0; i < 36; ++i) acc[i] = 0.0f;

    auto compute_stage = [&](int buf) {
        const float* x1b = x1rb + buf * BUFF;
        const float* x2b = x2rb + buf * BUFF;
        #pragma unroll
        for (int c = 0; c < CB; ++c) {
            float4 a  = *reinterpret_cast<const float4*>(x1b + c * (TH * TW));
            float4 b0 = *reinterpret_cast<const float4*>(x2b + c * (16 * S2F));
            float4 b1 = *reinterpret_cast<const float4*>(x2b + c * (16 * S2F) + 4);
            float4 b2 = *reinterpret_cast<const float4*>(x2b + c * (16 * S2F) + 8);
            const float av[4] = {a.x, a.y, a.z, a.w};
            const float v[12] = {b0.x, b0.y, b0.z, b0.w,
                                 b1.x, b1.y, b1.z, b1.w,
                                 b2.x, b2.y, b2.z, b2.w};
            #pragma unroll
            for (int p = 0; p < 4; ++p)
                #pragma unroll
                for (int kx = 0; kx < 9; ++kx)
                    acc[p * 9 + kx] = fmaf(av[p], v[p + kx], acc[p * 9 + kx]);
        }
    };

    // ---------- 3-buffer ring, one barrier per stage ----------
    load_stage(0);
    load_stage(1);

    int bufl = 2;   // load target for stage s+2
    #pragma unroll 1
    for (int s = 0; s < NSTAGE; ++s) {
        if (s < NSTAGE - 1) asm volatile("cp.async.wait_group 1;\n" ::: "memory");
        else                asm volatile("cp.async.wait_group 0;\n" ::: "memory");
        __syncthreads();  // buffer s ready; buffer bufl (== buffer of s-1) drained
        if (s < NSTAGE - 2) {
            load_stage(bufl);
            bufl = (bufl == 2) ? 0 : bufl + 1;
        }
        const int bc = (s < 3) ? s : ((s - 3) % 3 == 0 ? 0 : ((s - 3) % 3 == 1 ? 1 : 2));
        compute_stage(s % 3);
        (void)bc;
    }

    // ---------- epilogue ----------
    const float inv = 1.0f / (float)Cimg;
    float* op = out + ((size_t)(n * 81 + ky * 9) * (Himg * Wimg))
                    + (size_t)(h0 + ty) * Wimg + w0 + wg * 4;
    #pragma unroll
    for (int kx = 0; kx < 9; ++kx) {
        float4 r;
        r.x = acc[0 * 9 + kx] * inv;
        r.y = acc[1 * 9 + kx] * inv;
        r.z = acc[2 * 9 + kx] * inv;
        r.w = acc[3 * 9 + kx] * inv;
        *reinterpret_cast<float4*>(op + (size_t)kx * (Himg * Wimg)) = r;
    }
}

extern "C" void kernel_launch(void* const* d_in, const int* in_sizes, int n_in,
                              void* d_out, int out_size) {
    const float* x1 = (const float*)d_in[0];
    const float* x2 = (const float*)d_in[1];
    float* out = (float*)d_out;

    cudaFuncSetAttribute(corr_kernel, cudaFuncAttributeMaxDynamicSharedMemorySize,
                         SMEM_BYTES);

    dim3 block(8, 8, 9);                 // 576 threads
    dim3 grid(Wimg / TW, Himg / TH, 4);  // 1024 blocks
    corr_kernel<<<grid, block, SMEM_BYTES>>>(x1, x2, out);
}